// round 12
// baseline (speedup 1.0000x reference)
#include <cuda_runtime.h>

#define NB 32
#define LL 1024
#define TT 64
#define KSEG 9
#define NCH (2 * KSEG - 2)   // 16 chains per batch

#define FMA2(d,a,b,c) asm("fma.rn.f32x2 %0, %1, %2, %3;" : "=l"(d) : "l"(a), "l"(b), "l"(c))
#define MUL2(d,a,b)   asm("mul.rn.f32x2 %0, %1, %2;"     : "=l"(d) : "l"(a), "l"(b))
#define ADD2(d,a,b)   asm("add.rn.f32x2 %0, %1, %2;"     : "=l"(d) : "l"(a), "l"(b))
#define UNPACK2(lo,hi,v) asm("mov.b64 {%0,%1}, %2;" : "=f"(lo), "=f"(hi) : "l"(v))
#define PACK2(v,lo,hi)   asm("mov.b64 %0, {%1,%2};" : "=l"(v) : "f"(lo), "f"(hi))

// segment cut points: c[k] = (k*1023)/9
__device__ __constant__ int d_cut[KSEG + 1] =
    {0, 113, 227, 341, 454, 568, 682, 795, 909, 1023};

// device-global scratch (sanctioned no-alloc scratch)
__device__ float g_vec[NB][NCH][TT];   // normalized chain output vectors
__device__ int   g_ex[NB][NCH];        // integer pow2 exponent offsets
__device__ int   g_cnt[NB];            // arrival counters (self-resetting)

// smem slot for state s: half-B offset by 4 floats (16B) to kill the
// 2-way bank conflict between the two half-group broadcast lines
__device__ __forceinline__ int slot(int s) { return s + ((s & 32) >> 3); }

__global__ __launch_bounds__(64)
void crf_seg_kernel(const float* __restrict__ logits,     // [B,L,T]
                    const float* __restrict__ trans,      // [T,T]
                    const float* __restrict__ start_s,    // [T]
                    const float* __restrict__ end_s,      // [T]
                    const int* __restrict__ mask,         // [B,L] bool as int32
                    float* __restrict__ out)              // [B]
{
    const int b   = blockIdx.x >> 4;
    const int cid = blockIdx.x & 15;     // chain id 0..15, one per 64-thr CTA
    const int tid = threadIdx.x;
    const int w   = tid >> 5;            // warp: output group
    const int l   = tid & 31;
    const int h   = l >> 4;              // input half this thread reads
    const int q   = l & 15;
    const int j0  = w * 32 + 2 * q;      // this thread's output pair
    const int j1  = j0 + 1;
    const int gi  = 16 * w + q;          // float2 index of (j0,j1)
    const bool lw = (l < 16);            // designated writer lanes
    const int wslot = j0 + 4 * w;        // padded slot of j0 (j0&32 == 32w)

    // x vector: half-A at [0..32), half-B at [36..68); double buffered
    __shared__ __align__(16) float xs[2][72];
    __shared__ int s_red[2];
    __shared__ int s_end;
    __shared__ int s_win;

    // ---- end_idx = count(mask != 0) - 1 ; mask stored as int32 ----
    {
        const int4* mb = reinterpret_cast<const int4*>(mask + (size_t)b * LL);
        int cnt = 0;
        #pragma unroll
        for (int p = 0; p < 4; ++p) {
            int4 m = mb[tid * 4 + p];    // 64 thr * 16 ints = 1024
            cnt += (m.x != 0) + (m.y != 0) + (m.z != 0) + (m.w != 0);
        }
        #pragma unroll
        for (int o = 16; o > 0; o >>= 1) cnt += __shfl_xor_sync(~0u, cnt, o);
        if ((tid & 31) == 0) s_red[tid >> 5] = cnt;
        __syncthreads();
        if (tid == 0) s_end = s_red[0] + s_red[1] - 1;
        __syncthreads();
    }
    const int endi = s_end;
    const bool generic = (endi != 1023);
    if (generic && cid != 0) return;

    const bool bwd = (!generic) && (cid >= KSEG - 1);   // cid >= 8
    const float esc = generic ? 1.0f : 0.0078125f;      // fold 2^-7 into E'

    // ---- E' slices: 16 input-pairs (over this thread's half) per output ----
    unsigned long long ea[16], eb[16];   // for j0 / j1
    #pragma unroll
    for (int p = 0; p < 16; ++p) {
        int i0 = 32 * h + 2 * p, i1 = i0 + 1;
        float a0, a1, b0, b1;
        if (!bwd) {        // columns of E
            a0 = __expf(__ldg(&trans[i0 * TT + j0])) * esc;
            a1 = __expf(__ldg(&trans[i1 * TT + j0])) * esc;
            b0 = __expf(__ldg(&trans[i0 * TT + j1])) * esc;
            b1 = __expf(__ldg(&trans[i1 * TT + j1])) * esc;
        } else {           // rows of E
            a0 = __expf(__ldg(&trans[j0 * TT + i0])) * esc;
            a1 = __expf(__ldg(&trans[j0 * TT + i1])) * esc;
            b0 = __expf(__ldg(&trans[j1 * TT + i0])) * esc;
            b1 = __expf(__ldg(&trans[j1 * TT + i1])) * esc;
        }
        PACK2(ea[p], a0, a1);
        PACK2(eb[p], b0, b1);
    }

    const float*  lg0 = logits + (size_t)b * LL * TT;
    const float2* lgp = reinterpret_cast<const float2*>(lg0) + gi;  // [t*32]
    int buf = 0;

    // half-dot for (j0, j1) over this thread's input half, then cross-half
    // combine via shfl.xor(16): both mates end with the full dots.
    auto dot2 = [&](float& d0, float& d1) {
        const ulonglong2* bp =
            reinterpret_cast<const ulonglong2*>(&xs[buf][36 * h]);
        unsigned long long A0, A1, A2, A3, B0, B1, B2, B3;
        {
            ulonglong2 v = bp[0], u = bp[1];
            MUL2(A0, v.x, ea[0]); MUL2(B0, v.x, eb[0]);
            MUL2(A1, v.y, ea[1]); MUL2(B1, v.y, eb[1]);
            MUL2(A2, u.x, ea[2]); MUL2(B2, u.x, eb[2]);
            MUL2(A3, u.y, ea[3]); MUL2(B3, u.y, eb[3]);
        }
        {
            ulonglong2 v = bp[2], u = bp[3];
            FMA2(A0, v.x, ea[4], A0); FMA2(B0, v.x, eb[4], B0);
            FMA2(A1, v.y, ea[5], A1); FMA2(B1, v.y, eb[5], B1);
            FMA2(A2, u.x, ea[6], A2); FMA2(B2, u.x, eb[6], B2);
            FMA2(A3, u.y, ea[7], A3); FMA2(B3, u.y, eb[7], B3);
        }
        {
            ulonglong2 v = bp[4], u = bp[5];
            FMA2(A0, v.x, ea[8],  A0); FMA2(B0, v.x, eb[8],  B0);
            FMA2(A1, v.y, ea[9],  A1); FMA2(B1, v.y, eb[9],  B1);
            FMA2(A2, u.x, ea[10], A2); FMA2(B2, u.x, eb[10], B2);
            FMA2(A3, u.y, ea[11], A3); FMA2(B3, u.y, eb[11], B3);
        }
        {
            ulonglong2 v = bp[6], u = bp[7];
            FMA2(A0, v.x, ea[12], A0); FMA2(B0, v.x, eb[12], B0);
            FMA2(A1, v.y, ea[13], A1); FMA2(B1, v.y, eb[13], B1);
            FMA2(A2, u.x, ea[14], A2); FMA2(B2, u.x, eb[14], B2);
            FMA2(A3, u.y, ea[15], A3); FMA2(B3, u.y, eb[15], B3);
        }
        ADD2(A0, A0, A1); ADD2(A2, A2, A3); ADD2(A0, A0, A2);
        ADD2(B0, B0, B1); ADD2(B2, B2, B3); ADD2(B0, B0, B2);
        float lo, hi;
        UNPACK2(lo, hi, A0); d0 = lo + hi;
        UNPACK2(lo, hi, B0); d1 = lo + hi;
        d0 += __shfl_xor_sync(~0u, d0, 16);
        d1 += __shfl_xor_sync(~0u, d1, 16);
    };

    auto step_fast = [&](float2 g) {
        float d0, d1;
        dot2(d0, d1);
        float y0 = d0 * __expf(g.x);
        float y1 = d1 * __expf(g.y);
        if (lw)
            *reinterpret_cast<float2*>(&xs[buf ^ 1][wslot]) =
                make_float2(y0, y1);
        buf ^= 1;
        __syncthreads();
    };

    auto writeout = [&](int S) {
        float bb = xs[buf][0];               // broadcast
        int   ex = ((__float_as_int(bb) >> 23) & 255) - 127;
        float scale = __int_as_float((127 - ex) << 23);
        g_vec[b][cid][tid] = xs[buf][slot(tid)] * scale;
        if (tid == 0) g_ex[b][cid] = ex + 7 * S;
    };

    if (generic) {
        // ==== correct fallback: full forward with per-step pow2 renorm ====
        const float er0 = __ldg(&end_s[j0]), er1 = __ldg(&end_s[j1]);
        xs[0][slot(tid)] = __expf(lg0[tid] + __ldg(&start_s[tid]) +
                                  ((endi == 0) ? __ldg(&end_s[tid]) : 0.f));
        __syncthreads();
        int exoff = 0;
        #pragma unroll 1
        for (int t = 1; t <= endi; ++t) {
            float bb = xs[buf][0];
            int   ex = ((__float_as_int(bb) >> 23) & 255) - 127;
            float scale = __int_as_float((127 - ex) << 23);
            float2 g = lgp[(size_t)t * 32];
            float e0 = (t == endi) ? er0 : 0.f;
            float e1 = (t == endi) ? er1 : 0.f;
            float d0, d1;
            dot2(d0, d1);
            float y0 = d0 * (scale * __expf(g.x + e0));
            float y1 = d1 * (scale * __expf(g.y + e1));
            if (lw)
                *reinterpret_cast<float2*>(&xs[buf ^ 1][wslot]) =
                    make_float2(y0, y1);
            exoff += ex;
            buf ^= 1;
            __syncthreads();
        }
        float s = xs[buf][slot(tid)];
        #pragma unroll
        for (int o = 16; o > 0; o >>= 1) s += __shfl_xor_sync(~0u, s, o);
        if ((tid & 31) == 0)
            reinterpret_cast<float*>(s_red)[tid >> 5] = s;
        __syncthreads();
        if (tid == 0) {
            float tot = reinterpret_cast<float*>(s_red)[0] +
                        reinterpret_cast<float*>(s_red)[1];
            out[b] = __int2float_rn(exoff) * 0.693147180559945f + __logf(tot);
        }
        return;
    }

    if (!bwd) {
        // ========== forward chains: R (cid 0), Q_k (cid k-1, k=2..8) ==========
        int lo, hi;
        if (cid == 0) {
            lo = 1; hi = d_cut[1];
            xs[0][slot(tid)] = __expf(lg0[tid] + __ldg(&start_s[tid]));
        } else {
            int k = cid + 1;
            lo = d_cut[k - 1] + 1; hi = d_cut[k];
            xs[0][slot(tid)] = 1.0f;
        }
        __syncthreads();

        float2 g0 = lgp[(size_t)(lo    ) * 32];
        float2 g1 = lgp[(size_t)(lo + 1) * 32];
        float2 g2 = lgp[(size_t)(lo + 2) * 32];
        float2 g3 = lgp[(size_t)(lo + 3) * 32];
        float2 g4 = lgp[(size_t)(lo + 4) * 32];
        float2 g5 = lgp[(size_t)(lo + 5) * 32];
        int t = lo;
        #pragma unroll 1
        for (; t + 5 <= hi; t += 6) {
            step_fast(g0); g0 = lgp[(size_t)(t + 6)  * 32];
            step_fast(g1); g1 = lgp[(size_t)(t + 7)  * 32];
            step_fast(g2); g2 = lgp[(size_t)(t + 8)  * 32];
            step_fast(g3); g3 = lgp[(size_t)(t + 9)  * 32];
            step_fast(g4); g4 = lgp[(size_t)(t + 10) * 32];
            step_fast(g5); g5 = lgp[(size_t)(t + 11) * 32];
        }
        if (t <= hi) { step_fast(g0); ++t; }
        if (t <= hi) { step_fast(g1); ++t; }
        if (t <= hi) { step_fast(g2); ++t; }
        if (t <= hi) { step_fast(g3); ++t; }
        if (t <= hi) { step_fast(g4); ++t; }

        writeout(hi - lo + 1);
    } else {
        // ===== backward chains: P_k (cid k+6, k=2..8), W (cid 15) =====
        int lo0, hi0, S;
        if (cid == NCH - 1) {            // W
            lo0 = d_cut[KSEG - 1] + 1;   // 910
            hi0 = 1022;
            xs[0][slot(tid)] =
                __expf(lg0[(size_t)1023 * TT + tid] + __ldg(&end_s[tid]));
            S = 1023 - d_cut[KSEG - 1];
        } else {                         // P_k
            int k = cid - 6;
            lo0 = d_cut[k - 1] + 1;
            hi0 = d_cut[k] - 1;
            xs[0][slot(tid)] = __expf(lg0[(size_t)d_cut[k] * TT + tid]);
            S = d_cut[k] - d_cut[k - 1];
        }
        __syncthreads();

        float2 g0 = lgp[(size_t)(hi0    ) * 32];
        float2 g1 = lgp[(size_t)(hi0 - 1) * 32];
        float2 g2 = lgp[(size_t)(hi0 - 2) * 32];
        float2 g3 = lgp[(size_t)(hi0 - 3) * 32];
        float2 g4 = lgp[(size_t)(hi0 - 4) * 32];
        float2 g5 = lgp[(size_t)(hi0 - 5) * 32];
        int t = hi0;
        #pragma unroll 1
        for (; t - 5 >= lo0; t -= 6) {
            step_fast(g0); g0 = lgp[(size_t)(t - 6)  * 32];
            step_fast(g1); g1 = lgp[(size_t)(t - 7)  * 32];
            step_fast(g2); g2 = lgp[(size_t)(t - 8)  * 32];
            step_fast(g3); g3 = lgp[(size_t)(t - 9)  * 32];
            step_fast(g4); g4 = lgp[(size_t)(t - 10) * 32];
            step_fast(g5); g5 = lgp[(size_t)(t - 11) * 32];
        }
        if (t >= lo0) { step_fast(g0); --t; }
        if (t >= lo0) { step_fast(g1); --t; }
        if (t >= lo0) { step_fast(g2); --t; }
        if (t >= lo0) { step_fast(g3); --t; }
        if (t >= lo0) { step_fast(g4); --t; }

        step_fast(make_float2(0.f, 0.f));   // epilogue matvec p = E'u (eg=1)
        writeout(S);
    }

    // ---- fused combine: last CTA of this batch reduces all 16 chains ----
    __threadfence();
    __syncthreads();
    if (tid == 0) {
        int old = atomicAdd(&g_cnt[b], 1);
        s_win = (old == NCH - 1);
    }
    __syncthreads();
    if (!s_win) return;
    __threadfence();

    if (tid < 32) {
        const int ll = tid;
        float va[NCH], vb[NCH];
        #pragma unroll
        for (int c = 0; c < NCH; ++c) {
            va[c] = g_vec[b][c][ll];
            vb[c] = g_vec[b][c][ll + 32];
        }

        float acc = 0.0f;
        #pragma unroll
        for (int k = 2; k <= KSEG - 1; ++k) {
            float d = va[k + 6] * va[k - 2] + vb[k + 6] * vb[k - 2];
            float s = va[k - 1] + vb[k - 1];
            #pragma unroll
            for (int o = 16; o > 0; o >>= 1) {
                d += __shfl_xor_sync(~0u, d, o);
                s += __shfl_xor_sync(~0u, s, o);
            }
            acc += __logf(d) - __logf(s);
        }
        {
            float d = va[NCH - 1] * va[KSEG - 2] + vb[NCH - 1] * vb[KSEG - 2];
            #pragma unroll
            for (int o = 16; o > 0; o >>= 1) d += __shfl_xor_sync(~0u, d, o);
            acc += __logf(d);
        }

        if (ll == 0) {
            int ex = g_ex[b][0] + g_ex[b][NCH - 1];
            #pragma unroll
            for (int c = NCH / 2; c <= NCH - 2; ++c) ex += g_ex[b][c];
            out[b] = acc + __int2float_rn(ex) * 0.693147180559945f;
            g_cnt[b] = 0;                // reset for next graph replay
        }
    }
}

extern "C" void kernel_launch(void* const* d_in, const int* in_sizes, int n_in,
                              void* d_out, int out_size) {
    const float* logits        = (const float*)d_in[0];
    const float* transitions   = (const float*)d_in[1];
    const float* start_states  = (const float*)d_in[2];
    const float* end_states    = (const float*)d_in[3];
    const int*   mask          = (const int*)d_in[4];
    float* out = (float*)d_out;
    (void)in_sizes; (void)n_in; (void)out_size;

    crf_seg_kernel<<<NB * NCH, 64>>>(logits, transitions, start_states,
                                     end_states, mask, out);
}

// round 13
// speedup vs baseline: 1.1360x; 1.1360x over previous
#include <cuda_runtime.h>

#define NB 32
#define LL 1024
#define TT 64
#define KSEG 17
#define NCH (2 * KSEG - 2)   // 32 chains per batch

#define FMA2(d,a,b,c) asm("fma.rn.f32x2 %0, %1, %2, %3;" : "=l"(d) : "l"(a), "l"(b), "l"(c))
#define MUL2(d,a,b)   asm("mul.rn.f32x2 %0, %1, %2;"     : "=l"(d) : "l"(a), "l"(b))
#define ADD2(d,a,b)   asm("add.rn.f32x2 %0, %1, %2;"     : "=l"(d) : "l"(a), "l"(b))
#define UNPACK2(lo,hi,v) asm("mov.b64 {%0,%1}, %2;" : "=f"(lo), "=f"(hi) : "l"(v))
#define PACK2(v,lo,hi)   asm("mov.b64 %0, {%1,%2};" : "=l"(v) : "f"(lo), "f"(hi))

// segment cut points: c[k] = floor(k*1023/16)
__device__ __constant__ int d_cut[KSEG + 1] =
    {0, 63, 127, 191, 255, 319, 383, 447, 511,
     575, 639, 703, 767, 831, 895, 959, 1023};

// device-global scratch (sanctioned no-alloc scratch)
__device__ float g_vec[NB][NCH][TT];   // normalized chain output vectors
__device__ int   g_ex[NB][NCH];        // integer pow2 exponent offsets
__device__ int   g_cnt[NB];            // arrival counters (self-resetting)

__global__ __launch_bounds__(64)
void crf_seg_kernel(const float* __restrict__ logits,     // [B,L,T]
                    const float* __restrict__ trans,      // [T,T]
                    const float* __restrict__ start_s,    // [T]
                    const float* __restrict__ end_s,      // [T]
                    const int* __restrict__ mask,         // [B,L] bool as int32
                    float* __restrict__ out)              // [B]
{
    const int b   = blockIdx.x >> 5;
    const int cid = blockIdx.x & 31;     // chain id 0..31, one per 64-thr CTA
    const int tid = threadIdx.x;         // = output state j, 0..63

    __shared__ __align__(16) float xs[2][TT];
    __shared__ int s_red[2];
    __shared__ int s_end;
    __shared__ int s_win;

    // ---- end_idx = count(mask != 0) - 1 ; mask stored as int32 ----
    {
        const int4* mb = reinterpret_cast<const int4*>(mask + (size_t)b * LL);
        int cnt = 0;
        #pragma unroll
        for (int q = 0; q < 4; ++q) {
            int4 m = mb[tid * 4 + q];    // 64 thr * 16 ints = 1024
            cnt += (m.x != 0) + (m.y != 0) + (m.z != 0) + (m.w != 0);
        }
        #pragma unroll
        for (int o = 16; o > 0; o >>= 1) cnt += __shfl_xor_sync(~0u, cnt, o);
        if ((tid & 31) == 0) s_red[tid >> 5] = cnt;
        __syncthreads();
        if (tid == 0) s_end = s_red[0] + s_red[1] - 1;
        __syncthreads();
    }
    const int endi = s_end;
    const bool generic = (endi != 1023);
    if (generic && cid != 0) return;

    const bool bwd = (!generic) && (cid >= KSEG - 1);   // cid >= 16
    const float esc = generic ? 1.0f : 0.0078125f;      // fold 2^-7 into E'

    // ---- E' slice for output state tid: 32 packed input-pairs ----
    unsigned long long e2[32];
    #pragma unroll
    for (int p = 0; p < 32; ++p) {
        int i0 = bwd ? (tid * TT + 2 * p)     : ((2 * p)     * TT + tid);
        int i1 = bwd ? (tid * TT + 2 * p + 1) : ((2 * p + 1) * TT + tid);
        float lo = __expf(__ldg(&trans[i0])) * esc;
        float hi = __expf(__ldg(&trans[i1])) * esc;
        PACK2(e2[p], lo, hi);
    }

    const float* lg = logits + (size_t)b * LL * TT + tid;
    int buf = 0;

    auto dot = [&]() -> float {
        const ulonglong2* bp = reinterpret_cast<const ulonglong2*>(xs[buf]);
        unsigned long long A0, A1, A2, A3;
        {
            ulonglong2 v = bp[0], w = bp[1];
            MUL2(A0, v.x, e2[0]); MUL2(A1, v.y, e2[1]);
            MUL2(A2, w.x, e2[2]); MUL2(A3, w.y, e2[3]);
        }
        {
            ulonglong2 v = bp[2], w = bp[3];
            FMA2(A0, v.x, e2[4], A0); FMA2(A1, v.y, e2[5], A1);
            FMA2(A2, w.x, e2[6], A2); FMA2(A3, w.y, e2[7], A3);
        }
        {
            ulonglong2 v = bp[4], w = bp[5];
            FMA2(A0, v.x, e2[8],  A0); FMA2(A1, v.y, e2[9],  A1);
            FMA2(A2, w.x, e2[10], A2); FMA2(A3, w.y, e2[11], A3);
        }
        {
            ulonglong2 v = bp[6], w = bp[7];
            FMA2(A0, v.x, e2[12], A0); FMA2(A1, v.y, e2[13], A1);
            FMA2(A2, w.x, e2[14], A2); FMA2(A3, w.y, e2[15], A3);
        }
        {
            ulonglong2 v = bp[8], w = bp[9];
            FMA2(A0, v.x, e2[16], A0); FMA2(A1, v.y, e2[17], A1);
            FMA2(A2, w.x, e2[18], A2); FMA2(A3, w.y, e2[19], A3);
        }
        {
            ulonglong2 v = bp[10], w = bp[11];
            FMA2(A0, v.x, e2[20], A0); FMA2(A1, v.y, e2[21], A1);
            FMA2(A2, w.x, e2[22], A2); FMA2(A3, w.y, e2[23], A3);
        }
        {
            ulonglong2 v = bp[12], w = bp[13];
            FMA2(A0, v.x, e2[24], A0); FMA2(A1, v.y, e2[25], A1);
            FMA2(A2, w.x, e2[26], A2); FMA2(A3, w.y, e2[27], A3);
        }
        {
            ulonglong2 v = bp[14], w = bp[15];
            FMA2(A0, v.x, e2[28], A0); FMA2(A1, v.y, e2[29], A1);
            FMA2(A2, w.x, e2[30], A2); FMA2(A3, w.y, e2[31], A3);
        }
        ADD2(A0, A0, A1); ADD2(A2, A2, A3); ADD2(A0, A0, A2);
        float lo, hi;
        UNPACK2(lo, hi, A0);
        return lo + hi;
    };

    auto step_fast = [&](float graw) {
        float d = dot();
        xs[buf ^ 1][tid] = d * __expf(graw);
        buf ^= 1;
        __syncthreads();
    };

    auto writeout = [&](float x, int S) {
        float bb = xs[buf][0];
        int   ex = ((__float_as_int(bb) >> 23) & 255) - 127;
        float scale = __int_as_float((127 - ex) << 23);
        g_vec[b][cid][tid] = x * scale;
        if (tid == 0) g_ex[b][cid] = ex + 7 * S;
    };

    if (generic) {
        // ==== correct fallback: full forward with per-step pow2 renorm ====
        xs[0][tid] = __expf(lg[0] + __ldg(&start_s[tid]) +
                            ((endi == 0) ? __ldg(&end_s[tid]) : 0.f));
        __syncthreads();
        int exoff = 0;
        #pragma unroll 1
        for (int t = 1; t <= endi; ++t) {
            float bb = xs[buf][0];
            int   ex = ((__float_as_int(bb) >> 23) & 255) - 127;
            float scale = __int_as_float((127 - ex) << 23);
            float g = lg[(size_t)t * TT] +
                      ((t == endi) ? __ldg(&end_s[tid]) : 0.f);
            float d = dot();
            xs[buf ^ 1][tid] = d * (scale * __expf(g));
            exoff += ex;
            buf ^= 1;
            __syncthreads();
        }
        float s = xs[buf][tid];
        #pragma unroll
        for (int o = 16; o > 0; o >>= 1) s += __shfl_xor_sync(~0u, s, o);
        if ((tid & 31) == 0)
            reinterpret_cast<float*>(s_red)[tid >> 5] = s;
        __syncthreads();
        if (tid == 0) {
            float tot = reinterpret_cast<float*>(s_red)[0] +
                        reinterpret_cast<float*>(s_red)[1];
            out[b] = __int2float_rn(exoff) * 0.693147180559945f + __logf(tot);
        }
        return;
    }

    if (!bwd) {
        // ====== forward chains: R (cid 0), Q_k (cid k-1, k=2..KSEG-1) ======
        int lo, hi;
        if (cid == 0) {
            lo = 1; hi = d_cut[1];
            xs[0][tid] = __expf(lg[0] + __ldg(&start_s[tid]));
        } else {
            int k = cid + 1;
            lo = d_cut[k - 1] + 1; hi = d_cut[k];
            xs[0][tid] = 1.0f;
        }
        __syncthreads();

        // distance-6 prefetch
        float g0 = lg[(size_t)(lo    ) * TT];
        float g1 = lg[(size_t)(lo + 1) * TT];
        float g2 = lg[(size_t)(lo + 2) * TT];
        float g3 = lg[(size_t)(lo + 3) * TT];
        float g4 = lg[(size_t)(lo + 4) * TT];
        float g5 = lg[(size_t)(lo + 5) * TT];
        int t = lo;
        #pragma unroll 1
        for (; t + 5 <= hi; t += 6) {
            step_fast(g0); g0 = lg[(size_t)(t + 6)  * TT];
            step_fast(g1); g1 = lg[(size_t)(t + 7)  * TT];
            step_fast(g2); g2 = lg[(size_t)(t + 8)  * TT];
            step_fast(g3); g3 = lg[(size_t)(t + 9)  * TT];
            step_fast(g4); g4 = lg[(size_t)(t + 10) * TT];
            step_fast(g5); g5 = lg[(size_t)(t + 11) * TT];
        }
        if (t <= hi) { step_fast(g0); ++t; }
        if (t <= hi) { step_fast(g1); ++t; }
        if (t <= hi) { step_fast(g2); ++t; }
        if (t <= hi) { step_fast(g3); ++t; }
        if (t <= hi) { step_fast(g4); ++t; }

        writeout(xs[buf][tid], hi - lo + 1);
    } else {
        // == backward chains: P_k (cid k+KSEG-3, k=2..KSEG-1), W (cid NCH-1) ==
        int lo0, hi0, S;
        if (cid == NCH - 1) {            // W
            lo0 = d_cut[KSEG - 1] + 1;   // 960
            hi0 = 1022;
            xs[0][tid] = __expf(lg[(size_t)1023 * TT] + __ldg(&end_s[tid]));
            S = 1023 - d_cut[KSEG - 1];
        } else {                         // P_k
            int k = cid - (KSEG - 3);    // cid - 14
            lo0 = d_cut[k - 1] + 1;
            hi0 = d_cut[k] - 1;
            xs[0][tid] = __expf(lg[(size_t)d_cut[k] * TT]);
            S = d_cut[k] - d_cut[k - 1];
        }
        __syncthreads();

        float g0 = lg[(size_t)(hi0    ) * TT];
        float g1 = lg[(size_t)(hi0 - 1) * TT];
        float g2 = lg[(size_t)(hi0 - 2) * TT];
        float g3 = lg[(size_t)(hi0 - 3) * TT];
        float g4 = lg[(size_t)(hi0 - 4) * TT];
        float g5 = lg[(size_t)(hi0 - 5) * TT];
        int t = hi0;
        #pragma unroll 1
        for (; t - 5 >= lo0; t -= 6) {
            step_fast(g0); g0 = lg[(size_t)(t - 6)  * TT];
            step_fast(g1); g1 = lg[(size_t)(t - 7)  * TT];
            step_fast(g2); g2 = lg[(size_t)(t - 8)  * TT];
            step_fast(g3); g3 = lg[(size_t)(t - 9)  * TT];
            step_fast(g4); g4 = lg[(size_t)(t - 10) * TT];
            step_fast(g5); g5 = lg[(size_t)(t - 11) * TT];
        }
        if (t >= lo0) { step_fast(g0); --t; }
        if (t >= lo0) { step_fast(g1); --t; }
        if (t >= lo0) { step_fast(g2); --t; }
        if (t >= lo0) { step_fast(g3); --t; }
        if (t >= lo0) { step_fast(g4); --t; }

        float d = dot();                 // epilogue matvec p = E' u, no eg
        writeout(d, S);
    }

    // ---- fused combine: last CTA of this batch reduces all 32 chains ----
    __threadfence();
    __syncthreads();
    if (tid == 0) {
        int old = atomicAdd(&g_cnt[b], 1);
        s_win = (old == NCH - 1);
    }
    __syncthreads();
    if (!s_win) return;
    __threadfence();

    if (tid < 32) {
        const int l = tid;
        float va[NCH], vb[NCH];
        #pragma unroll
        for (int c = 0; c < NCH; ++c) {
            va[c] = g_vec[b][c][l];
            vb[c] = g_vec[b][c][l + 32];
        }

        float acc = 0.0f;
        #pragma unroll
        for (int k = 2; k <= KSEG - 1; ++k) {
            float d = va[k + KSEG - 3] * va[k - 2] + vb[k + KSEG - 3] * vb[k - 2];
            float s = va[k - 1] + vb[k - 1];
            #pragma unroll
            for (int o = 16; o > 0; o >>= 1) {
                d += __shfl_xor_sync(~0u, d, o);
                s += __shfl_xor_sync(~0u, s, o);
            }
            acc += __logf(d) - __logf(s);
        }
        {
            float d = va[NCH - 1] * va[KSEG - 2] + vb[NCH - 1] * vb[KSEG - 2];
            #pragma unroll
            for (int o = 16; o > 0; o >>= 1) d += __shfl_xor_sync(~0u, d, o);
            acc += __logf(d);
        }

        if (l == 0) {
            int ex = g_ex[b][0] + g_ex[b][NCH - 1];
            #pragma unroll
            for (int c = KSEG - 1; c <= NCH - 2; ++c) ex += g_ex[b][c];
            out[b] = acc + __int2float_rn(ex) * 0.693147180559945f;
            g_cnt[b] = 0;                // reset for next graph replay
        }
    }
}

extern "C" void kernel_launch(void* const* d_in, const int* in_sizes, int n_in,
                              void* d_out, int out_size) {
    const float* logits        = (const float*)d_in[0];
    const float* transitions   = (const float*)d_in[1];
    const float* start_states  = (const float*)d_in[2];
    const float* end_states    = (const float*)d_in[3];
    const int*   mask          = (const int*)d_in[4];
    float* out = (float*)d_out;
    (void)in_sizes; (void)n_in; (void)out_size;

    crf_seg_kernel<<<NB * NCH, 64>>>(logits, transitions, start_states,
                                     end_states, mask, out);
}